// round 8
// baseline (speedup 1.0000x reference)
#include <cuda_runtime.h>
#include <cstdint>

// DisulfideEnergy: sulfur-pair energy scatter + fused residue reduction.
//
// Output (single f32 buffer):
//   [0 .. 64000)              resi_energy (8,4,500,4)
//   [64000 .. 2064000)        atom_energy (500000,4)
//   [2064000 .. 6064000)      sulfur      (4000000) as 0.0/1.0

#define N_CHAINS   4
#define N_RES      500
#define SG_CODE    7
#define MAX_ATOMS  500000
#define MAX_WORDS  ((MAX_ATOMS + 31) / 32)   // 15625
#define DEPTH      3                          // cp.async ring stages
#define PBLOCK     1024                       // pair_kernel block size

__device__ __align__(16) uint32_t g_sgmask[MAX_WORDS + 32];

// ---------------------------------------------------------------------------
// Kernel 1: build SG bitmask (4 atoms/thread, MLP=4) AND zero the
// resi+atom_energy output regions.
// ---------------------------------------------------------------------------
__global__ void mask_zero_kernel(const int* __restrict__ desc,
                                 float* __restrict__ out,
                                 int n_atoms, int zero_float4s)
{
    int base = blockIdx.x * 1024;
    int an[4];
#pragma unroll
    for (int u = 0; u < 4; u++) {
        int a = base + u * 256 + threadIdx.x;
        an[u] = (a < n_atoms) ? __ldcs(desc + 4 * a) : 0;   // at_name column
    }
#pragma unroll
    for (int u = 0; u < 4; u++) {
        int a = base + u * 256 + threadIdx.x;
        unsigned ball = __ballot_sync(0xffffffffu, an[u] == SG_CODE);
        if ((threadIdx.x & 31) == 0 && a < n_atoms)
            g_sgmask[a >> 5] = ball;
    }

    // zero resi + atom_energy regions (grid-stride, float4)
    float4 z = make_float4(0.f, 0.f, 0.f, 0.f);
    int stride = gridDim.x * blockDim.x;
    for (int t = blockIdx.x * blockDim.x + threadIdx.x;
         t < zero_float4s; t += stride)
        __stcs(reinterpret_cast<float4*>(out) + t, z);
}

// ---------------------------------------------------------------------------
// Heavy path: only true sulfur pairs (~1/1600). Updates atomE AND resi.
// noinline keeps its register demand out of the hot loop.
// ---------------------------------------------------------------------------
__device__ __noinline__ void heavy_pair(int i, int j,
                                        const float* __restrict__ coords,
                                        const int4* __restrict__ desc4,
                                        const uint32_t* __restrict__ amask,
                                        float* __restrict__ atomE,
                                        float* __restrict__ resi)
{
    float dx = __ldg(coords + 3 * i + 0) - __ldg(coords + 3 * j + 0) + 1e-6f;
    float dy = __ldg(coords + 3 * i + 1) - __ldg(coords + 3 * j + 1) + 1e-6f;
    float dz = __ldg(coords + 3 * i + 2) - __ldg(coords + 3 * j + 2) + 1e-6f;
    float dist = sqrtf(dx * dx + dy * dy + dz * dz);

    int4 di = __ldg(desc4 + i);   // (at_name, resnum, batch, chain)
    int4 dj = __ldg(desc4 + j);

    float rd  = fabsf((float)(di.y - dj.y));
    float rds = (rd > 0.f) ? rd : 1.0f;

    // -0.001*298.0 = -0.298
    float energy = -0.298f * (2.1f + 2.9823825f * logf(rds))
                 + 5.0f * fabsf(dist - 2.04f);
    float net = 0.5f * energy;

    int flat_i = (di.z * N_CHAINS + di.w) * N_RES + di.y;
    int flat_j = (dj.z * N_CHAINS + dj.w) * N_RES + dj.y;

    uint4 mi = *reinterpret_cast<const uint4*>(amask + 4 * (size_t)i);
    uint4 mj = *reinterpret_cast<const uint4*>(amask + 4 * (size_t)j);

#define ALT(A, MI, MJ)                                                       \
    if ((MI) && (MJ)) {                                                      \
        atomicAdd(atomE + 4 * (size_t)i + (A), net);                         \
        atomicAdd(atomE + 4 * (size_t)j + (A), net);                         \
        atomicAdd(resi  + 4 * (size_t)flat_i + (A), net);                    \
        atomicAdd(resi  + 4 * (size_t)flat_j + (A), net);                    \
    }
    ALT(0, mi.x, mj.x)
    ALT(1, mi.y, mj.y)
    ALT(2, mi.z, mj.z)
    ALT(3, mi.w, mj.w)
#undef ALT
}

// ---------------------------------------------------------------------------
// cp.async helpers (per-thread groups; no CTA barrier needed since each
// thread reads only the 16B slot it wrote).
// ---------------------------------------------------------------------------
__device__ __forceinline__ void cp_async16(uint32_t smem_addr, const void* gptr)
{
    asm volatile("cp.async.cg.shared.global [%0], [%1], 16;"
                 :: "r"(smem_addr), "l"(gptr) : "memory");
}
__device__ __forceinline__ void cp_commit()
{
    asm volatile("cp.async.commit_group;" ::: "memory");
}
__device__ __forceinline__ void cp_wait_allbutone()
{
    asm volatile("cp.async.wait_group %0;" :: "n"(DEPTH - 2) : "memory");
}

// ---------------------------------------------------------------------------
// Kernel 2: pair sweep. SG bitmask in smem (62.5 KB) + DEPTH-stage cp.async
// ring (16B/thread/stage). 64 warps/SM, ~2 chunks (32B/thread) in flight.
// ---------------------------------------------------------------------------
__global__ void __launch_bounds__(PBLOCK, 2)
pair_kernel(const int4* __restrict__ pairs2,
            const float* __restrict__ coords,
            const int4* __restrict__ desc4,
            const uint32_t* __restrict__ amask,
            float* __restrict__ out,
            int n_pairs, int n_atoms, int resi_floats)
{
    extern __shared__ __align__(16) uint32_t smem_dyn[];
    uint32_t* smask = smem_dyn;
    int nwords = (n_atoms + 31) >> 5;
    int mask_words_padded = (nwords + 3) & ~3;              // 16B aligned
    int4* ring = reinterpret_cast<int4*>(smem_dyn + mask_words_padded);

    // stage mask (vectorized)
    {
        int nw4 = nwords >> 2;
        const uint4* gm4 = reinterpret_cast<const uint4*>(g_sgmask);
        uint4* sm4 = reinterpret_cast<uint4*>(smask);
        for (int w = threadIdx.x; w < nw4; w += blockDim.x)
            sm4[w] = gm4[w];
        for (int w = (nw4 << 2) + threadIdx.x; w < nwords; w += blockDim.x)
            smask[w] = g_sgmask[w];
    }
    __syncthreads();

    float* resi  = out;
    float* atomE = out + resi_floats;
    float* sout  = atomE + 4 * (size_t)n_atoms;

    int n2 = n_pairs >> 1;                     // int4 groups (2 pairs each)
    int stride = gridDim.x * blockDim.x;
    int idx = blockIdx.x * blockDim.x + threadIdx.x;

    // per-thread ring slots: ring[slot * PBLOCK + tid]
    uint32_t slot_addr[DEPTH];
#pragma unroll
    for (int d = 0; d < DEPTH; d++)
        slot_addr[d] = (uint32_t)__cvta_generic_to_shared(
                           ring + d * PBLOCK + threadIdx.x);

    // prologue: issue DEPTH-1 chunks
#pragma unroll
    for (int d = 0; d < DEPTH - 1; d++) {
        int pidx = idx + d * stride;
        if (pidx < n2) cp_async16(slot_addr[d], pairs2 + pidx);
        cp_commit();
    }

    int rd_slot = 0;
    int wr_slot = DEPTH - 1;
    while (idx < n2) {
        cp_wait_allbutone();                   // oldest chunk landed
        int4 a = ring[rd_slot * PBLOCK + threadIdx.x];

        // issue chunk DEPTH-1 iterations ahead
        int pidx = idx + (DEPTH - 1) * stride;
        if (pidx < n2) cp_async16(slot_addr[wr_slot], pairs2 + pidx);
        cp_commit();

        // first lookup unconditional, second predicated (p ~ 1/40)
#define BIT1(I) ((smask[(unsigned)(I) >> 5] >> ((I) & 31)) & 1u)
        unsigned s0 = BIT1(a.x); if (s0) s0 = BIT1(a.y);
        unsigned s1 = BIT1(a.z); if (s1) s1 = BIT1(a.w);
#undef BIT1

        float2 so;
        so.x = s0 ? 1.0f : 0.0f;
        so.y = s1 ? 1.0f : 0.0f;
        __stcs(reinterpret_cast<float2*>(sout) + idx, so);

        if (s0) heavy_pair(a.x, a.y, coords, desc4, amask, atomE, resi);
        if (s1) heavy_pair(a.z, a.w, coords, desc4, amask, atomE, resi);

        idx += stride;
        rd_slot = (rd_slot + 1 == DEPTH) ? 0 : rd_slot + 1;
        wr_slot = (wr_slot + 1 == DEPTH) ? 0 : wr_slot + 1;
    }

    // tail: odd pair (zero here, kept general)
    if ((n_pairs & 1) && blockIdx.x == 0 && threadIdx.x == 0) {
        const int* pp = reinterpret_cast<const int*>(pairs2);
        int i = pp[2 * (n_pairs - 1)], j = pp[2 * (n_pairs - 1) + 1];
        unsigned s = (smask[i >> 5] >> (i & 31))
                   & (smask[j >> 5] >> (j & 31)) & 1u;
        sout[n_pairs - 1] = s ? 1.0f : 0.0f;
        if (s) heavy_pair(i, j, coords, desc4, amask, atomE, resi);
    }
}

// ---------------------------------------------------------------------------
extern "C" void kernel_launch(void* const* d_in, const int* in_sizes, int n_in,
                              void* d_out, int out_size)
{
    const float*    coords = (const float*)d_in[0];
    const int*      desc   = (const int*)d_in[1];
    const int*      pairs  = (const int*)d_in[2];
    const uint32_t* amask  = (const uint32_t*)d_in[3];
    float*          out    = (float*)d_out;

    int n_atoms = in_sizes[0] / 3;
    int n_pairs = in_sizes[2] / 2;
    int n_alt   = in_sizes[3] / n_atoms;                      // 4
    int resi_floats = out_size - n_atoms * n_alt - n_pairs;   // 64000

    int nwords = (n_atoms + 31) >> 5;
    int mask_words_padded = (nwords + 3) & ~3;
    size_t smem = (size_t)mask_words_padded * 4
                + (size_t)DEPTH * PBLOCK * 16;                // 62512 + 49152

    cudaFuncSetAttribute(pair_kernel,
                         cudaFuncAttributeMaxDynamicSharedMemorySize,
                         (int)smem);

    // Mask build + zero resi/atomE regions in one kernel.
    int mblocks = (n_atoms + 1023) / 1024;
    int zero_float4s = (resi_floats + n_atoms * n_alt) / 4;
    mask_zero_kernel<<<mblocks, 256>>>(desc, out, n_atoms, zero_float4s);

    // 2 CTAs/SM x 1024 threads = 64 warps/SM; cp.async ring keeps
    // 32B/thread in flight without register cost.
    pair_kernel<<<296, PBLOCK, smem>>>((const int4*)pairs, coords,
                                       (const int4*)desc, amask,
                                       out, n_pairs, n_atoms, resi_floats);
}

// round 9
// speedup vs baseline: 1.0677x; 1.0677x over previous
#include <cuda_runtime.h>
#include <cstdint>

// DisulfideEnergy: sulfur-pair energy scatter + fused residue reduction.
//
// Output (single f32 buffer):
//   [0 .. 64000)              resi_energy (8,4,500,4)
//   [64000 .. 2064000)        atom_energy (500000,4)
//   [2064000 .. 6064000)      sulfur      (4000000) as 0.0/1.0
//
// Structure: mask_zero (primary) builds the SG bitmask + zeroes output
// regions; pair_kernel (secondary, PDL) launches early, prefetches its
// first pairs chunk during the primary, then grid-dependency-syncs before
// reading the mask / issuing atomics.

#define N_CHAINS   4
#define N_RES      500
#define SG_CODE    7
#define MAX_ATOMS  500000
#define MAX_WORDS  ((MAX_ATOMS + 31) / 32)   // 15625
#define PBLOCK     1024

__device__ __align__(16) uint32_t g_sgmask[MAX_WORDS + 32];

// ---------------------------------------------------------------------------
// Primary: build SG bitmask (4 atoms/thread, MLP=4) AND zero resi+atomE.
// Triggers PDL completion at entry so the pair kernel can launch early.
// ---------------------------------------------------------------------------
__global__ void mask_zero_kernel(const int* __restrict__ desc,
                                 float* __restrict__ out,
                                 int n_atoms, int zero_float4s)
{
    cudaTriggerProgrammaticLaunchCompletion();

    int base = blockIdx.x * 1024;
    int an[4];
#pragma unroll
    for (int u = 0; u < 4; u++) {
        int a = base + u * 256 + threadIdx.x;
        an[u] = (a < n_atoms) ? __ldcs(desc + 4 * a) : 0;   // at_name column
    }
#pragma unroll
    for (int u = 0; u < 4; u++) {
        int a = base + u * 256 + threadIdx.x;
        unsigned ball = __ballot_sync(0xffffffffu, an[u] == SG_CODE);
        if ((threadIdx.x & 31) == 0 && a < n_atoms)
            g_sgmask[a >> 5] = ball;
    }

    // zero resi + atom_energy regions (grid-stride, float4)
    float4 z = make_float4(0.f, 0.f, 0.f, 0.f);
    int stride = gridDim.x * blockDim.x;
    for (int t = blockIdx.x * blockDim.x + threadIdx.x;
         t < zero_float4s; t += stride)
        __stcs(reinterpret_cast<float4*>(out) + t, z);
}

// ---------------------------------------------------------------------------
// Heavy path: only true sulfur pairs (~1/1600). Updates atomE AND resi.
// noinline keeps its register demand out of the hot loop.
// ---------------------------------------------------------------------------
__device__ __noinline__ void heavy_pair(int i, int j,
                                        const float* __restrict__ coords,
                                        const int4* __restrict__ desc4,
                                        const uint32_t* __restrict__ amask,
                                        float* __restrict__ atomE,
                                        float* __restrict__ resi)
{
    float dx = __ldg(coords + 3 * i + 0) - __ldg(coords + 3 * j + 0) + 1e-6f;
    float dy = __ldg(coords + 3 * i + 1) - __ldg(coords + 3 * j + 1) + 1e-6f;
    float dz = __ldg(coords + 3 * i + 2) - __ldg(coords + 3 * j + 2) + 1e-6f;
    float dist = sqrtf(dx * dx + dy * dy + dz * dz);

    int4 di = __ldg(desc4 + i);   // (at_name, resnum, batch, chain)
    int4 dj = __ldg(desc4 + j);

    float rd  = fabsf((float)(di.y - dj.y));
    float rds = (rd > 0.f) ? rd : 1.0f;

    // -0.001*298.0 = -0.298
    float energy = -0.298f * (2.1f + 2.9823825f * logf(rds))
                 + 5.0f * fabsf(dist - 2.04f);
    float net = 0.5f * energy;

    int flat_i = (di.z * N_CHAINS + di.w) * N_RES + di.y;
    int flat_j = (dj.z * N_CHAINS + dj.w) * N_RES + dj.y;

    uint4 mi = *reinterpret_cast<const uint4*>(amask + 4 * (size_t)i);
    uint4 mj = *reinterpret_cast<const uint4*>(amask + 4 * (size_t)j);

#define ALT(A, MI, MJ)                                                       \
    if ((MI) && (MJ)) {                                                      \
        atomicAdd(atomE + 4 * (size_t)i + (A), net);                         \
        atomicAdd(atomE + 4 * (size_t)j + (A), net);                         \
        atomicAdd(resi  + 4 * (size_t)flat_i + (A), net);                    \
        atomicAdd(resi  + 4 * (size_t)flat_j + (A), net);                    \
    }
    ALT(0, mi.x, mj.x)
    ALT(1, mi.y, mj.y)
    ALT(2, mi.z, mj.z)
    ALT(3, mi.w, mj.w)
#undef ALT
}

// ---------------------------------------------------------------------------
// Secondary: pair sweep. SG bitmask in shared memory (62.5 KB).
// 1024 thr x 2 CTAs/SM = 64 warps/SM (32 regs). 2 pairs/iter + 1-deep
// register prefetch. PDL: first pairs load issued BEFORE the grid-dep sync.
// ---------------------------------------------------------------------------
__global__ void __launch_bounds__(PBLOCK, 2)
pair_kernel(const int4* __restrict__ pairs2,
            const float* __restrict__ coords,
            const int4* __restrict__ desc4,
            const uint32_t* __restrict__ amask,
            float* __restrict__ out,
            int n_pairs, int n_atoms, int resi_floats)
{
    extern __shared__ __align__(16) uint32_t smask[];
    int nwords = (n_atoms + 31) >> 5;

    int n2 = n_pairs >> 1;                     // int4 groups (2 pairs each)
    int stride = gridDim.x * blockDim.x;
    int idx = blockIdx.x * blockDim.x + threadIdx.x;

    // Pre-sync: prefetch first pairs chunk (independent of primary's output).
    int4 a;
    bool valid = idx < n2;
    if (valid) a = __ldcs(pairs2 + idx);

    // Wait for mask build + output zeroing to be fully visible.
    cudaGridDependencySynchronize();

    // stage mask (vectorized)
    {
        int nw4 = nwords >> 2;
        const uint4* gm4 = reinterpret_cast<const uint4*>(g_sgmask);
        uint4* sm4 = reinterpret_cast<uint4*>(smask);
        for (int w = threadIdx.x; w < nw4; w += blockDim.x)
            sm4[w] = gm4[w];
        for (int w = (nw4 << 2) + threadIdx.x; w < nwords; w += blockDim.x)
            smask[w] = g_sgmask[w];
    }
    __syncthreads();

    float* resi  = out;
    float* atomE = out + resi_floats;
    float* sout  = atomE + 4 * (size_t)n_atoms;

    while (valid) {
        // prefetch next iteration's pairs (hides DRAM latency)
        int nidx = idx + stride;
        bool nvalid = nidx < n2;
        int4 b;
        if (nvalid) b = __ldcs(pairs2 + nidx);

        // first lookup unconditional, second predicated (p ~ 1/40)
#define BIT1(I) ((smask[(unsigned)(I) >> 5] >> ((I) & 31)) & 1u)
        unsigned s0 = BIT1(a.x); if (s0) s0 = BIT1(a.y);
        unsigned s1 = BIT1(a.z); if (s1) s1 = BIT1(a.w);
#undef BIT1

        float2 so;
        so.x = s0 ? 1.0f : 0.0f;
        so.y = s1 ? 1.0f : 0.0f;
        __stcs(reinterpret_cast<float2*>(sout) + idx, so);

        if (s0) heavy_pair(a.x, a.y, coords, desc4, amask, atomE, resi);
        if (s1) heavy_pair(a.z, a.w, coords, desc4, amask, atomE, resi);

        a = b; idx = nidx; valid = nvalid;
    }

    // tail: odd pair (zero here, kept general)
    if ((n_pairs & 1) && blockIdx.x == 0 && threadIdx.x == 0) {
        const int* pp = reinterpret_cast<const int*>(pairs2);
        int i = pp[2 * (n_pairs - 1)], j = pp[2 * (n_pairs - 1) + 1];
        unsigned s = (smask[i >> 5] >> (i & 31))
                   & (smask[j >> 5] >> (j & 31)) & 1u;
        sout[n_pairs - 1] = s ? 1.0f : 0.0f;
        if (s) heavy_pair(i, j, coords, desc4, amask, atomE, resi);
    }
}

// ---------------------------------------------------------------------------
extern "C" void kernel_launch(void* const* d_in, const int* in_sizes, int n_in,
                              void* d_out, int out_size)
{
    const float*    coords = (const float*)d_in[0];
    const int*      desc   = (const int*)d_in[1];
    const int*      pairs  = (const int*)d_in[2];
    const uint32_t* amask  = (const uint32_t*)d_in[3];
    float*          out    = (float*)d_out;

    int n_atoms = in_sizes[0] / 3;
    int n_pairs = in_sizes[2] / 2;
    int n_alt   = in_sizes[3] / n_atoms;                      // 4
    int resi_floats = out_size - n_atoms * n_alt - n_pairs;   // 64000

    int nwords = (n_atoms + 31) >> 5;
    size_t smem = (size_t)((nwords + 3) & ~3) * 4;            // 62512 B

    cudaFuncSetAttribute(pair_kernel,
                         cudaFuncAttributeMaxDynamicSharedMemorySize,
                         (int)smem);

    // Primary: mask build + zero resi/atomE regions.
    int mblocks = (n_atoms + 1023) / 1024;
    int zero_float4s = (resi_floats + n_atoms * n_alt) / 4;
    mask_zero_kernel<<<mblocks, 256>>>(desc, out, n_atoms, zero_float4s);

    // Secondary with programmatic dependent launch: overlaps its CTA
    // placement + first pairs prefetch with the primary's execution.
    {
        cudaLaunchConfig_t cfg = {};
        cfg.gridDim  = dim3(296, 1, 1);       // 2 CTAs/SM x 148 SMs
        cfg.blockDim = dim3(PBLOCK, 1, 1);
        cfg.dynamicSmemBytes = smem;
        cfg.stream = 0;
        cudaLaunchAttribute attr[1];
        attr[0].id = cudaLaunchAttributeProgrammaticStreamSerialization;
        attr[0].val.programmaticStreamSerializationAllowed = 1;
        cfg.attrs = attr;
        cfg.numAttrs = 1;

        const int4* pairs4 = (const int4*)pairs;
        const int4* desc4  = (const int4*)desc;
        cudaLaunchKernelEx(&cfg, pair_kernel,
                           pairs4, coords, desc4, amask,
                           out, n_pairs, n_atoms, resi_floats);
    }
}

// round 10
// speedup vs baseline: 1.0786x; 1.0103x over previous
#include <cuda_runtime.h>
#include <cstdint>

// DisulfideEnergy: sulfur-pair energy scatter + fused residue reduction.
//
// Output (single f32 buffer):
//   [0 .. 64000)              resi_energy (8,4,500,4)
//   [64000 .. 2064000)        atom_energy (500000,4)
//   [2064000 .. 6064000)      sulfur      (4000000) as 0.0/1.0

#define N_CHAINS   4
#define N_RES      500
#define SG_CODE    7
#define MAX_ATOMS  500000
#define MAX_WORDS  ((MAX_ATOMS + 31) / 32)   // 15625
#define PBLOCK     1024

__device__ __align__(16) uint32_t g_sgmask[MAX_WORDS + 32];

// ---------------------------------------------------------------------------
// Kernel 1: build SG bitmask (4 atoms/thread, MLP=4) AND zero resi+atomE.
// ---------------------------------------------------------------------------
__global__ void mask_zero_kernel(const int* __restrict__ desc,
                                 float* __restrict__ out,
                                 int n_atoms, int zero_float4s)
{
    int base = blockIdx.x * 1024;
    int an[4];
#pragma unroll
    for (int u = 0; u < 4; u++) {
        int a = base + u * 256 + threadIdx.x;
        an[u] = (a < n_atoms) ? __ldcs(desc + 4 * a) : 0;   // at_name column
    }
#pragma unroll
    for (int u = 0; u < 4; u++) {
        int a = base + u * 256 + threadIdx.x;
        unsigned ball = __ballot_sync(0xffffffffu, an[u] == SG_CODE);
        if ((threadIdx.x & 31) == 0 && a < n_atoms)
            g_sgmask[a >> 5] = ball;
    }

    // zero resi + atom_energy regions (grid-stride, float4)
    float4 z = make_float4(0.f, 0.f, 0.f, 0.f);
    int stride = gridDim.x * blockDim.x;
    for (int t = blockIdx.x * blockDim.x + threadIdx.x;
         t < zero_float4s; t += stride)
        __stcs(reinterpret_cast<float4*>(out) + t, z);
}

// ---------------------------------------------------------------------------
// Heavy path: one true sulfur pair. Updates atomE AND resi.
// ---------------------------------------------------------------------------
__device__ __forceinline__ void heavy_pair(int i, int j,
                                           const float* __restrict__ coords,
                                           const int4* __restrict__ desc4,
                                           const uint32_t* __restrict__ amask,
                                           float* __restrict__ atomE,
                                           float* __restrict__ resi)
{
    float dx = __ldg(coords + 3 * i + 0) - __ldg(coords + 3 * j + 0) + 1e-6f;
    float dy = __ldg(coords + 3 * i + 1) - __ldg(coords + 3 * j + 1) + 1e-6f;
    float dz = __ldg(coords + 3 * i + 2) - __ldg(coords + 3 * j + 2) + 1e-6f;
    float dist = sqrtf(dx * dx + dy * dy + dz * dz);

    int4 di = __ldg(desc4 + i);   // (at_name, resnum, batch, chain)
    int4 dj = __ldg(desc4 + j);

    float rd  = fabsf((float)(di.y - dj.y));
    float rds = (rd > 0.f) ? rd : 1.0f;

    // -0.001*298.0 = -0.298
    float energy = -0.298f * (2.1f + 2.9823825f * logf(rds))
                 + 5.0f * fabsf(dist - 2.04f);
    float net = 0.5f * energy;

    int flat_i = (di.z * N_CHAINS + di.w) * N_RES + di.y;
    int flat_j = (dj.z * N_CHAINS + dj.w) * N_RES + dj.y;

    uint4 mi = *reinterpret_cast<const uint4*>(amask + 4 * (size_t)i);
    uint4 mj = *reinterpret_cast<const uint4*>(amask + 4 * (size_t)j);

#define ALT(A, MI, MJ)                                                       \
    if ((MI) && (MJ)) {                                                      \
        atomicAdd(atomE + 4 * (size_t)i + (A), net);                         \
        atomicAdd(atomE + 4 * (size_t)j + (A), net);                         \
        atomicAdd(resi  + 4 * (size_t)flat_i + (A), net);                    \
        atomicAdd(resi  + 4 * (size_t)flat_j + (A), net);                    \
    }
    ALT(0, mi.x, mj.x)
    ALT(1, mi.y, mj.y)
    ALT(2, mi.z, mj.z)
    ALT(3, mi.w, mj.w)
#undef ALT
}

// Cold handler for a chunk of 2 pairs: single branch target in the hot loop.
__device__ __noinline__ void heavy_chunk(int4 a, unsigned s0, unsigned s1,
                                         const float* __restrict__ coords,
                                         const int4* __restrict__ desc4,
                                         const uint32_t* __restrict__ amask,
                                         float* __restrict__ atomE,
                                         float* __restrict__ resi)
{
    if (s0) heavy_pair(a.x, a.y, coords, desc4, amask, atomE, resi);
    if (s1) heavy_pair(a.z, a.w, coords, desc4, amask, atomE, resi);
}

// ---------------------------------------------------------------------------
// Kernel 2: pair sweep — BRANCHLESS hot loop.
// 1024 thr x 2 CTAs/SM = 64 warps/SM (32 regs). 2 pairs/iter.
// Per iteration: 1 clamped prefetch LDG (no guard branch), 4 unconditional
// LDS lookups, 1 STG.64, ONE rarely-taken branch to the cold handler.
// ---------------------------------------------------------------------------
__global__ void __launch_bounds__(PBLOCK, 2)
pair_kernel(const int4* __restrict__ pairs2,
            const float* __restrict__ coords,
            const int4* __restrict__ desc4,
            const uint32_t* __restrict__ amask,
            float* __restrict__ out,
            int n_pairs, int n_atoms, int resi_floats)
{
    extern __shared__ __align__(16) uint32_t smask[];
    int nwords = (n_atoms + 31) >> 5;

    // stage mask (vectorized)
    {
        int nw4 = nwords >> 2;
        const uint4* gm4 = reinterpret_cast<const uint4*>(g_sgmask);
        uint4* sm4 = reinterpret_cast<uint4*>(smask);
        for (int w = threadIdx.x; w < nw4; w += blockDim.x)
            sm4[w] = gm4[w];
        for (int w = (nw4 << 2) + threadIdx.x; w < nwords; w += blockDim.x)
            smask[w] = g_sgmask[w];
    }
    __syncthreads();

    float* resi  = out;
    float* atomE = out + resi_floats;
    float* sout  = atomE + 4 * (size_t)n_atoms;

    int n2 = n_pairs >> 1;                     // int4 groups (2 pairs each)
    int stride = gridDim.x * blockDim.x;
    int idx = blockIdx.x * blockDim.x + threadIdx.x;

    if (idx < n2) {
        int4 a = __ldcs(pairs2 + idx);         // first chunk

        do {
            // clamped unconditional prefetch (IMNMX, no branch)
            int nidx = idx + stride;
            int pidx = min(nidx, n2 - 1);
            int4 b = __ldcs(pairs2 + pidx);

            // unconditional mask lookups — pure LDS+ALU, branch-free
#define BIT(I) (smask[(unsigned)(I) >> 5] >> ((I) & 31))
            unsigned s0 = BIT(a.x) & BIT(a.y) & 1u;
            unsigned s1 = BIT(a.z) & BIT(a.w) & 1u;
#undef BIT

            float2 so;
            so.x = (float)s0;                  // I2F, branch-free
            so.y = (float)s1;
            __stcs(reinterpret_cast<float2*>(sout) + idx, so);

            // single rarely-taken branch (p ~ 1/800 per pair)
            if (s0 | s1)
                heavy_chunk(a, s0, s1, coords, desc4, amask, atomE, resi);

            a = b;
            idx = nidx;
        } while (idx < n2);
    }

    // tail: odd pair (zero here, kept general)
    if ((n_pairs & 1) && blockIdx.x == 0 && threadIdx.x == 0) {
        const int* pp = reinterpret_cast<const int*>(pairs2);
        int i = pp[2 * (n_pairs - 1)], j = pp[2 * (n_pairs - 1) + 1];
        unsigned s = (smask[i >> 5] >> (i & 31))
                   & (smask[j >> 5] >> (j & 31)) & 1u;
        sout[n_pairs - 1] = s ? 1.0f : 0.0f;
        if (s) heavy_pair(i, j, coords, desc4, amask, atomE, resi);
    }
}

// ---------------------------------------------------------------------------
extern "C" void kernel_launch(void* const* d_in, const int* in_sizes, int n_in,
                              void* d_out, int out_size)
{
    const float*    coords = (const float*)d_in[0];
    const int*      desc   = (const int*)d_in[1];
    const int*      pairs  = (const int*)d_in[2];
    const uint32_t* amask  = (const uint32_t*)d_in[3];
    float*          out    = (float*)d_out;

    int n_atoms = in_sizes[0] / 3;
    int n_pairs = in_sizes[2] / 2;
    int n_alt   = in_sizes[3] / n_atoms;                      // 4
    int resi_floats = out_size - n_atoms * n_alt - n_pairs;   // 64000

    int nwords = (n_atoms + 31) >> 5;
    size_t smem = (size_t)((nwords + 3) & ~3) * 4;            // 62512 B

    cudaFuncSetAttribute(pair_kernel,
                         cudaFuncAttributeMaxDynamicSharedMemorySize,
                         (int)smem);

    // Mask build + zero resi/atomE regions in one kernel.
    int mblocks = (n_atoms + 1023) / 1024;
    int zero_float4s = (resi_floats + n_atoms * n_alt) / 4;
    mask_zero_kernel<<<mblocks, 256>>>(desc, out, n_atoms, zero_float4s);

    // 2 CTAs/SM x 1024 threads = 64 warps/SM.
    pair_kernel<<<296, PBLOCK, smem>>>((const int4*)pairs, coords,
                                       (const int4*)desc, amask,
                                       out, n_pairs, n_atoms, resi_floats);
}